// round 9
// baseline (speedup 1.0000x reference)
#include <cuda_runtime.h>
#include <cuda_bf16.h>
#include <cstdint>
#include <math.h>

// ---------------------------------------------------------------------------
// SimpleModelQ collapsed, single persistent kernel + 3 memset reset nodes.
//   qk[b] = (M @ archi[b] + c)/sqrt(258);  M = kW^T qW, c = kW^T qb
//   (q.kb score shift constant per batch -> cancels in softmax; kb unused)
//   fbar = softmax-weighted feat mean; res=vW@fbar+vb; MLP; out.
// 256 CTAs x 256 thr (2/SM via 108KB smem -> all co-resident -> grid syncs).
// Attention: TMA 3-stage smem ring + warp-local softmax (no mainloop barriers
// except 1 recycle-sync/chunk). MLP: atomic split-K accumulation.
// ---------------------------------------------------------------------------

#define S_     1024
#define LAST_  258
#define FEAT_  255
#define NCTA_  256

// ---- device scratch ----
__device__ float4 g_qkp[64 * 256];      // k0 stage-1 partials
__device__ float4 g_qkp2[8 * 256];      // k0 stage-2 partials
__device__ float  g_uT[256 * 256];      // [f][2b+half] unnormalized sums
__device__ float2 g_ml[256];            // [2b+half] (m, l)
__device__ float  g_res[1024 * 128];
__device__ float  g_h1[512 * 128];      // atomic-accumulated; memset 0/launch
__device__ float  g_h2[256 * 128];      // atomic-accumulated; memset 0/launch
__device__ int    g_sync[8];            // memset 0/launch

// smem layout (floats)
#define SBUF   0                         // 3 stages x 32x258 = 24768
#define SQK    24768                     // 264 (qk, padded; reused as bias slice)
#define SRED   (SQK + 264)               // 8*256 = 2048
#define SMLW   (SRED + 2048)             // 16 (8 x float2)
#define SSW    (SMLW + 16)               // 64
#define SMB    (SSW + 64)                // 6 (3 x u64 mbarriers; byte off %8==0)
#define STOT   (SMB + 8)
#define SMEM_BYTES (STOT * 4)            // ~108.7 KB

__device__ __forceinline__ unsigned long long dup_f32(float a) {
    unsigned long long r;
    asm("mov.b64 %0, {%1, %1};" : "=l"(r) : "f"(a));
    return r;
}
__device__ __forceinline__ void fma_x2(unsigned long long& acc,
                                       unsigned long long a, unsigned long long w) {
    asm("fma.rn.f32x2 %0, %1, %2, %0;" : "+l"(acc) : "l"(a), "l"(w));
}
__device__ __forceinline__ void mul_x2(unsigned long long& d, unsigned long long a,
                                       unsigned long long b) {
    asm("mul.rn.f32x2 %0, %1, %2;" : "=l"(d) : "l"(a), "l"(b));
}
__device__ __forceinline__ void unpack_x2(unsigned long long v, float& lo, float& hi) {
    asm("mov.b64 {%0, %1}, %2;" : "=f"(lo), "=f"(hi) : "l"(v));
}

__device__ __forceinline__ void gsync(int i) {
    __syncthreads();
    if (threadIdx.x == 0) {
        __threadfence();
        atomicAdd(&g_sync[i], 1);
        while (*(volatile int*)&g_sync[i] < NCTA_) { }
        __threadfence();
    }
    __syncthreads();
}

__global__ void __launch_bounds__(256, 2)
fused_kernel(const float* __restrict__ input,
             const float* __restrict__ kW, const float* __restrict__ qW,
             const float* __restrict__ qb,
             const float* __restrict__ vW, const float* __restrict__ vb,
             const float* __restrict__ W1, const float* __restrict__ b1,
             const float* __restrict__ W2, const float* __restrict__ b2,
             const float* __restrict__ W3, const float* __restrict__ b3,
             float* __restrict__ out) {
    extern __shared__ float sm[];
    const int c    = blockIdx.x;
    const int tid  = threadIdx.x;
    const int lane = tid & 31, w = tid >> 5;
    const int ab = c >> 1, ahalf = c & 1;
    const uint32_t sb32 = (uint32_t)__cvta_generic_to_shared(sm);
    const uint32_t mb   = sb32 + SMB * 4;
    const float* gbase = input + (size_t)ab * S_ * LAST_;
    const float* hbase = gbase + (size_t)(ahalf * 512) * LAST_;

    // ---------- TMA ring: init + prefetch 3 chunks BEFORE k0 phases ----------
    auto issue = [&](int ch) {
        uint32_t bar = mb + (ch % 3) * 8;
        uint32_t dst = sb32 + (uint32_t)((SBUF + (ch % 3) * 32 * LAST_) * 4);
        const float* g = hbase + (size_t)ch * 32 * LAST_;
        asm volatile("mbarrier.arrive.expect_tx.shared.b64 _, [%0], %1;"
                     :: "r"(bar), "r"(33024u) : "memory");
        asm volatile("cp.async.bulk.shared::cta.global.mbarrier::complete_tx::bytes "
                     "[%0], [%1], %2, [%3];"
                     :: "r"(dst), "l"(g), "r"(33024u), "r"(bar) : "memory");
    };
    if (tid == 0) {
#pragma unroll
        for (int s = 0; s < 3; s++)
            asm volatile("mbarrier.init.shared.b64 [%0], 1;" :: "r"(mb + s * 8) : "memory");
        // fence init before TMA use (same thread: program order suffices for issue)
        asm volatile("fence.proxy.async.shared::cta;" ::: "memory");
        issue(0); issue(1); issue(2);
    }

    const float ar0 = gbase[FEAT_ + 0];
    const float ar1 = gbase[FEAT_ + 1];
    const float ar2 = gbase[FEAT_ + 2];

    // ---------- phase 0: k0 partials (CTAs 0..63, 16 h-rows each) ----------
    if (c < 64) {
        const int h0 = c * 16;
        if (tid < 64) {
            int hh = h0 + (tid >> 2), k = tid & 3;
            sm[SSW + tid] = (k < 3) ? qW[hh * 3 + k] : qb[hh];
        }
        __syncthreads();
        float m0 = 0.f, m1 = 0.f, m2 = 0.f, cc2 = 0.f;
        if (tid < FEAT_) {
#pragma unroll
            for (int i = 0; i < 16; i++) {
                float kv = kW[(size_t)(h0 + i) * FEAT_ + tid];
                m0 += kv * sm[SSW + i * 4 + 0];
                m1 += kv * sm[SSW + i * 4 + 1];
                m2 += kv * sm[SSW + i * 4 + 2];
                cc2 += kv * sm[SSW + i * 4 + 3];
            }
        }
        g_qkp[c * 256 + tid] = make_float4(m0, m1, m2, cc2);
    }
    gsync(0);
    if (c < 8) {
        float4 s = make_float4(0.f, 0.f, 0.f, 0.f);
#pragma unroll
        for (int p = 0; p < 8; p++) {
            float4 v = g_qkp[(c * 8 + p) * 256 + tid];
            s.x += v.x; s.y += v.y; s.z += v.z; s.w += v.w;
        }
        g_qkp2[c * 256 + tid] = s;
    }
    gsync(1);

    // ---------- qk vector ----------
    {
        float4 s = make_float4(0.f, 0.f, 0.f, 0.f);
#pragma unroll
        for (int p = 0; p < 8; p++) {
            float4 v = g_qkp2[p * 256 + tid];
            s.x += v.x; s.y += v.y; s.z += v.z; s.w += v.w;
        }
        float val = (s.x * ar0 + s.y * ar1 + s.z * ar2 + s.w) * rsqrtf(258.0f);
        sm[SQK + tid] = (tid < FEAT_) ? val : 0.f;
        if (tid < 8) sm[SQK + 256 + tid] = 0.f;
    }
    __syncthreads();

    unsigned long long q2[4];
#pragma unroll
    for (int j = 0; j < 4; j++)
        q2[j] = *(const unsigned long long*)(sm + SQK + j * 64 + lane * 2);

    // ---------- attention mainloop ----------
    float m_w = -INFINITY, l_w = 0.f;
    unsigned long long acc[4] = {0ull, 0ull, 0ull, 0ull};

    for (int ch = 0; ch < 16; ch++) {
        // wait chunk (per-thread parity wait)
        {
            uint32_t bar = mb + (ch % 3) * 8;
            uint32_t ph = (uint32_t)((ch / 3) & 1);
            uint32_t done;
            asm volatile("{\n\t.reg .pred p;\n\t"
                         "mbarrier.try_wait.parity.acquire.cta.shared::cta.b64 p, [%1], %2;\n\t"
                         "selp.b32 %0, 1, 0, p;\n\t}"
                         : "=r"(done) : "r"(bar), "r"(ph) : "memory");
            if (!done) {
                asm volatile("{\n\t.reg .pred P1;\n\t"
                             "WL_%=:\n\t"
                             "mbarrier.try_wait.parity.acquire.cta.shared::cta.b64 P1, [%0], %1, 0x989680;\n\t"
                             "@P1 bra.uni WD_%=;\n\t"
                             "bra.uni WL_%=;\n\t"
                             "WD_%=:\n\t}"
                             :: "r"(bar), "r"(ph) : "memory");
            }
        }

        // load 4 rows x 8 cols from smem stage into regs
        unsigned long long x[4][4];
        const float* cur = sm + SBUF + (ch % 3) * 32 * LAST_ + (size_t)(w * 4) * LAST_ + lane * 2;
#pragma unroll
        for (int i = 0; i < 4; i++)
#pragma unroll
            for (int j = 0; j < 4; j++)
                x[i][j] = *(const unsigned long long*)(cur + (size_t)i * LAST_ + j * 64);

        // scores
        float v[4];
#pragma unroll
        for (int i = 0; i < 4; i++) {
            unsigned long long va = 0ull;
#pragma unroll
            for (int j = 0; j < 4; j++) fma_x2(va, x[i][j], q2[j]);
            float lo, hi; unpack_x2(va, lo, hi);
            v[i] = lo + hi;
        }
#pragma unroll
        for (int o = 16; o; o >>= 1) {
#pragma unroll
            for (int i = 0; i < 4; i++)
                v[i] += __shfl_xor_sync(0xffffffffu, v[i], o);
        }
        // warp-local online softmax (v identical across lanes)
        float mc = fmaxf(fmaxf(v[0], v[1]), fmaxf(v[2], v[3]));
        float mnew  = fmaxf(m_w, mc);
        float alpha = __expf(m_w - mnew);
        float p0 = __expf(v[0] - mnew), p1 = __expf(v[1] - mnew);
        float p2 = __expf(v[2] - mnew), p3 = __expf(v[3] - mnew);
        l_w = l_w * alpha + (p0 + p1) + (p2 + p3);
        m_w = mnew;
        unsigned long long ap = dup_f32(alpha);
#pragma unroll
        for (int j = 0; j < 4; j++) mul_x2(acc[j], acc[j], ap);
        unsigned long long pp0 = dup_f32(p0), pp1 = dup_f32(p1);
        unsigned long long pp2 = dup_f32(p2), pp3 = dup_f32(p3);
#pragma unroll
        for (int j = 0; j < 4; j++) {
            fma_x2(acc[j], pp0, x[0][j]);
            fma_x2(acc[j], pp1, x[1][j]);
            fma_x2(acc[j], pp2, x[2][j]);
            fma_x2(acc[j], pp3, x[3][j]);
        }

        __syncthreads();                 // all warps done with stage ch%3
        if (ch + 3 < 16 && tid == 0) issue(ch + 3);
    }

    // ---------- attention epilogue: merge 8 warps, write (M,L,u) ----------
#pragma unroll
    for (int j = 0; j < 4; j++)
        *(unsigned long long*)(sm + SRED + w * 256 + j * 64 + lane * 2) = acc[j];
    if (lane == 0) ((float2*)(sm + SMLW))[w] = make_float2(m_w, l_w);
    __syncthreads();
    {
        float M = -INFINITY;
#pragma unroll
        for (int ww = 0; ww < 8; ww++)
            M = fmaxf(M, ((float2*)(sm + SMLW))[ww].x);
        float L = 0.f, u = 0.f;
#pragma unroll
        for (int ww = 0; ww < 8; ww++) {
            float2 mlv = ((float2*)(sm + SMLW))[ww];
            float e = __expf(mlv.x - M);
            L += e * mlv.y;
            u += e * sm[SRED + ww * 256 + tid];
        }
        g_uT[(size_t)tid * 256 + c] = u;       // [f][2b+half]
        if (tid == 0) g_ml[c] = make_float2(M, L);
    }
    gsync(2);

    const int b = tid & 127, h = tid >> 7;
    float* smw = sm;   // reuse stage area for MLP weight tiles

    // ---------- phase 1: res = vW @ fbar + vb (inline 2-half softmax merge) ----
    {
        float2 ml0 = g_ml[2 * b], ml1 = g_ml[2 * b + 1];
        float M  = fmaxf(ml0.x, ml1.x);
        float e0 = __expf(ml0.x - M), e1 = __expf(ml1.x - M);
        float invL = 1.0f / (e0 * ml0.y + e1 * ml1.y);
        float s0 = e0 * invL, s1 = e1 * invL;

        const int n0 = c * 4;
#pragma unroll
        for (int nn = 0; nn < 4; nn++)
            smw[tid * 6 + nn] = (tid < FEAT_) ? vW[(size_t)(n0 + nn) * FEAT_ + tid] : 0.f;
        __syncthreads();
        unsigned long long a1 = 0ull;
#pragma unroll 16
        for (int kk = 0; kk < 256; kk++) {
            float2 uv = *(const float2*)(g_uT + (size_t)kk * 256 + 2 * b);
            unsigned long long ap = dup_f32(s0 * uv.x + s1 * uv.y);
            fma_x2(a1, ap, *(const unsigned long long*)&smw[kk * 6 + h * 2]);
        }
        float lo, hi; unpack_x2(a1, lo, hi);
        int n = n0 + h * 2;
        g_res[(size_t)n * 128 + b]       = lo + vb[n];
        g_res[(size_t)(n + 1) * 128 + b] = hi + vb[n + 1];
    }
    gsync(3);

    // ---------- phase 2: h1 partials -> atomicAdd into g_h1 ----------
    {
        const int n0 = (c >> 3) * 16, ks = c & 7, k0 = ks * 128;
        if (tid < 128) {
#pragma unroll
            for (int nn = 0; nn < 16; nn++)
                smw[tid * 18 + nn] = W1[(size_t)(n0 + nn) * 1024 + k0 + tid];
        }
        __syncthreads();
        unsigned long long a4[4] = {0ull, 0ull, 0ull, 0ull};
#pragma unroll 16
        for (int kk = 0; kk < 128; kk++) {
            unsigned long long ap = dup_f32(g_res[(size_t)(k0 + kk) * 128 + b]);
            const float* wp = &smw[kk * 18 + h * 8];
            fma_x2(a4[0], ap, *(const unsigned long long*)(wp + 0));
            fma_x2(a4[1], ap, *(const unsigned long long*)(wp + 2));
            fma_x2(a4[2], ap, *(const unsigned long long*)(wp + 4));
            fma_x2(a4[3], ap, *(const unsigned long long*)(wp + 6));
        }
#pragma unroll
        for (int i = 0; i < 4; i++) {
            float lo, hi; unpack_x2(a4[i], lo, hi);
            int n = n0 + h * 8 + 2 * i;
            atomicAdd(&g_h1[(size_t)n * 128 + b], lo);
            atomicAdd(&g_h1[(size_t)(n + 1) * 128 + b], hi);
        }
        __syncthreads();
    }
    gsync(4);

    // ---------- phase 3: h2 partials (relu(h1+b1) read inline) ----------
    {
        const int n0 = (c >> 3) * 8, ks = c & 7, k0 = ks * 64;
        if (tid < 64) {
#pragma unroll
            for (int nn = 0; nn < 8; nn++)
                smw[tid * 10 + nn] = W2[(size_t)(n0 + nn) * 512 + k0 + tid];
            sm[SQK + tid] = b1[k0 + tid];
        }
        __syncthreads();
        unsigned long long a2[2] = {0ull, 0ull};
#pragma unroll 16
        for (int kk = 0; kk < 64; kk++) {
            float hv = fmaxf(g_h1[(size_t)(k0 + kk) * 128 + b] + sm[SQK + kk], 0.f);
            unsigned long long ap = dup_f32(hv);
            const float* wp = &smw[kk * 10 + h * 4];
            fma_x2(a2[0], ap, *(const unsigned long long*)(wp + 0));
            fma_x2(a2[1], ap, *(const unsigned long long*)(wp + 2));
        }
#pragma unroll
        for (int i = 0; i < 2; i++) {
            float lo, hi; unpack_x2(a2[i], lo, hi);
            int n = n0 + h * 4 + 2 * i;
            atomicAdd(&g_h2[(size_t)n * 128 + b], lo);
            atomicAdd(&g_h2[(size_t)(n + 1) * 128 + b], hi);
        }
        __syncthreads();
    }

    // ---------- phase 4: last-arriving CTA computes the final layer ----------
    __shared__ int who;
    __threadfence();
    __syncthreads();
    if (tid == 0) who = atomicAdd(&g_sync[5], 1);
    __syncthreads();
    if (who == NCTA_ - 1) {
        __threadfence();
        smw[tid]       = W3[tid];
        smw[256 + tid] = W3[256 + tid];
        sm[SQK + tid]  = b2[tid];
        __syncthreads();
        if (tid < 128) {
            float o0 = 0.f, o1 = 0.f;
#pragma unroll 16
            for (int k = 0; k < 256; k++) {
                float hh = fmaxf(g_h2[(size_t)k * 128 + tid] + sm[SQK + k], 0.f);
                o0 += hh * smw[k];
                o1 += hh * smw[256 + k];
            }
            ((float2*)out)[tid] = make_float2(o0 + b3[0], o1 + b3[1]);
        }
    }
}

// ===========================================================================
extern "C" void kernel_launch(void* const* d_in, const int* in_sizes, int n_in,
                              void* d_out, int out_size) {
    const float* input = (const float*)d_in[0];
    const float* kW = (const float*)d_in[1];
    // d_in[2] = kb: constant score shift per batch -> cancels in softmax
    const float* vW = (const float*)d_in[3];
    const float* vb = (const float*)d_in[4];
    const float* qW = (const float*)d_in[5];
    const float* qb = (const float*)d_in[6];
    const float* W1 = (const float*)d_in[7];
    const float* b1 = (const float*)d_in[8];
    const float* W2 = (const float*)d_in[9];
    const float* b2 = (const float*)d_in[10];
    const float* W3 = (const float*)d_in[11];
    const float* b3 = (const float*)d_in[12];
    float* out = (float*)d_out;

    cudaFuncSetAttribute(fused_kernel, cudaFuncAttributeMaxDynamicSharedMemorySize,
                         SMEM_BYTES);

    void *p_sync, *p_h1, *p_h2;
    cudaGetSymbolAddress(&p_sync, g_sync);
    cudaGetSymbolAddress(&p_h1, g_h1);
    cudaGetSymbolAddress(&p_h2, g_h2);
    cudaMemsetAsync(p_sync, 0, 8 * sizeof(int));
    cudaMemsetAsync(p_h1, 0, 512 * 128 * sizeof(float));
    cudaMemsetAsync(p_h2, 0, 256 * 128 * sizeof(float));

    fused_kernel<<<NCTA_, 256, SMEM_BYTES>>>(input, kW, qW, qb, vW, vb,
                                             W1, b1, W2, b2, W3, b3, out);
}